// round 4
// baseline (speedup 1.0000x reference)
#include <cuda_runtime.h>
#include <cstdint>
#include <cstddef>

// ----------------------------------------------------------------------------
// BlockCirculantLinear on GB300 (sm_103a, PTX target without 'a' suffix, so
// NO tcgen05 — use legacy mma.sync m16n8k8 tf32 tensor cores instead).
//   y[m, n] = sum_k x[m, k] * W[n, k] + bias[n]
//   W[nb*8+kk, ib*8+j] = circ[nb, ib, (kk - j) mod 8]
// Plan: (1) round x -> tf32 into g_X, (2) expand circ -> dense tf32 g_W,
//       (3) pipelined cp.async + ldmatrix + mma.sync TF32 GEMM.
// ----------------------------------------------------------------------------

#define BM 128
#define BN 128
#define BK 32
#define NSTAGE 3
#define MDIM 8192           // B*S
#define NDIM 4096           // OUT_F
#define KDIM 4096           // IN_F
#define NKITER (KDIM / BK)  // 128
#define THREADS 256

static constexpr int SMEM_TILES  = 0;
static constexpr int TILE_BYTES  = BM * BK * 4;      // 16384
static constexpr int STAGE_BYTES = 2 * TILE_BYTES;   // 32768 (A + B)
static constexpr int SMEM_TOTAL  = NSTAGE * STAGE_BYTES;  // 98304

__device__ float g_W[(size_t)NDIM * KDIM];   // expanded weight, [N][K], tf32-rounded
__device__ float g_X[(size_t)MDIM * KDIM];   // tf32-rounded activations

// ---------------- helpers ---------------------------------------------------

__device__ __forceinline__ uint32_t smem_u32(const void* p) {
    uint32_t a;
    asm("{ .reg .u64 t; cvta.to.shared.u64 t, %1; cvt.u32.u64 %0, t; }"
        : "=r"(a) : "l"(p));
    return a;
}

#define SWZ(off) ((off) ^ (((off) >> 3) & 0x70))

__device__ __forceinline__ void cp_async16(uint32_t dst, const float* src) {
    asm volatile("cp.async.cg.shared.global [%0], [%1], 16;"
                 :: "r"(dst), "l"(src));
}
__device__ __forceinline__ void cp_commit() {
    asm volatile("cp.async.commit_group;" ::: "memory");
}
template <int N> __device__ __forceinline__ void cp_wait() {
    asm volatile("cp.async.wait_group %0;" :: "n"(N) : "memory");
}

__device__ __forceinline__ float tf32r(float x) {
    uint32_t u;
    asm("cvt.rna.tf32.f32 %0, %1;" : "=r"(u) : "f"(x));
    return __uint_as_float(u);
}

__device__ __forceinline__ void ldsm4(uint32_t* r, uint32_t addr) {
    asm volatile("ldmatrix.sync.aligned.m8n8.x4.shared.b16 {%0,%1,%2,%3}, [%4];"
                 : "=r"(r[0]), "=r"(r[1]), "=r"(r[2]), "=r"(r[3]) : "r"(addr));
}

__device__ __forceinline__ void mma_tf32(float* c, const uint32_t* a,
                                         uint32_t b0, uint32_t b1) {
    asm volatile(
        "mma.sync.aligned.m16n8k8.row.col.f32.tf32.tf32.f32 "
        "{%0,%1,%2,%3}, {%4,%5,%6,%7}, {%8,%9}, {%0,%1,%2,%3};"
        : "+f"(c[0]), "+f"(c[1]), "+f"(c[2]), "+f"(c[3])
        : "r"(a[0]), "r"(a[1]), "r"(a[2]), "r"(a[3]), "r"(b0), "r"(b1));
}

// ---------------- Kernel 1: round x to tf32 ---------------------------------
__global__ void round_x_kernel(const float4* __restrict__ x) {
    int i = blockIdx.x * blockDim.x + threadIdx.x;   // MDIM*KDIM/4 threads
    float4 v = x[i];
    v.x = tf32r(v.x); v.y = tf32r(v.y); v.z = tf32r(v.z); v.w = tf32r(v.w);
    ((float4*)g_X)[i] = v;
}

// ---------------- Kernel 2: expand block-circulant weight (tf32-rounded) ----
__global__ void expand_w_kernel(const float* __restrict__ circ) {
    int idx = blockIdx.x * blockDim.x + threadIdx.x;   // NDIM*512
    int n  = idx >> 9;
    int ib = idx & 511;
    int nb = n >> 3;
    int kk = n & 7;
    const float* cp = circ + ((size_t)nb * 512 + ib) * 8;
    float c[8];
#pragma unroll
    for (int j = 0; j < 8; j++) c[j] = tf32r(cp[j]);
    float v[8];
#pragma unroll
    for (int j = 0; j < 8; j++) v[j] = c[(kk - j) & 7];
    float4* dst = (float4*)(g_W + (size_t)n * KDIM + ib * 8);
    dst[0] = make_float4(v[0], v[1], v[2], v[3]);
    dst[1] = make_float4(v[4], v[5], v[6], v[7]);
}

// ---------------- Kernel 3: TF32 mma.sync GEMM ------------------------------
// 256 threads = 8 warps as 2(m) x 4(n); warp tile 64x32; frags: 4 m x 4 n.

__global__ void __launch_bounds__(THREADS) bc_gemm(const float* __restrict__ bias,
                                                   float* __restrict__ C) {
    extern __shared__ char smem[];
    uint32_t sb0 = smem_u32(smem) + SMEM_TILES;
    const int tid = threadIdx.x;
    const int wid = tid >> 5;
    const int lid = tid & 31;
    const int wm = (wid >> 2) * 64;   // warp m offset in tile
    const int wn = (wid & 3) * 32;    // warp n offset in tile

    // Supertiled rasterization: 16 m-tiles x 32 n-tiles per group -> L2 reuse.
    const int NT = NDIM / BN;   // 32
    const int SUPER = 16;
    int bid = blockIdx.x;
    int grp = bid / (SUPER * NT);
    int rem = bid % (SUPER * NT);
    const int m0 = (grp * SUPER + (rem % SUPER)) * BM;
    const int n0 = (rem / SUPER) * BN;

    const float* Arow = g_X + (size_t)m0 * KDIM;
    const float* Brow = g_W + (size_t)n0 * KDIM;

    // Cooperative stage load: A tile 128x32 f32 + B tile 128x32 f32, swizzled.
    auto load_stage = [&](int s, int kiter) {
        uint32_t stg = sb0 + s * STAGE_BYTES;
        int k0 = kiter * BK;
#pragma unroll
        for (int q = 0; q < 4; q++) {
            int idx = tid + q * THREADS;      // 0..1023 chunks of 16B
            int row = idx >> 3;
            int ch  = idx & 7;
            uint32_t sw = SWZ((uint32_t)(row * 128 + ch * 16));
            cp_async16(stg + sw,              Arow + (size_t)row * KDIM + k0 + ch * 4);
            cp_async16(stg + TILE_BYTES + sw, Brow + (size_t)row * KDIM + k0 + ch * 4);
        }
        cp_commit();
    };

    float acc[4][4][4];
#pragma unroll
    for (int mf = 0; mf < 4; mf++)
#pragma unroll
        for (int nf = 0; nf < 4; nf++)
#pragma unroll
            for (int r = 0; r < 4; r++) acc[mf][nf][r] = 0.0f;

    load_stage(0, 0);
    load_stage(1, 1);

    const int lrow = lid & 15;          // ldmatrix row within 16-row block
    const int lcol = (lid >> 4) * 16;   // ldmatrix 16B column select

    for (int i = 0; i < NKITER; i++) {
        cp_wait<1>();
        __syncthreads();
        if (i + 2 < NKITER) load_stage((i + 2) % NSTAGE, i + 2);

        uint32_t Ab = sb0 + (i % NSTAGE) * STAGE_BYTES;
        uint32_t Bb = Ab + TILE_BYTES;

#pragma unroll
        for (int ks = 0; ks < 4; ks++) {
            uint32_t a[4][4];
#pragma unroll
            for (int mf = 0; mf < 4; mf++) {
                uint32_t off = (uint32_t)((wm + mf * 16 + lrow) * 128 + ks * 32 + lcol);
                ldsm4(a[mf], Ab + SWZ(off));
            }
            uint32_t b[2][4];   // [pair][r0=b0(even), r1=b0(odd), r2=b1(even), r3=b1(odd)]
#pragma unroll
            for (int p = 0; p < 2; p++) {
                uint32_t off = (uint32_t)((wn + p * 16 + lrow) * 128 + ks * 32 + lcol);
                ldsm4(b[p], Bb + SWZ(off));
            }
#pragma unroll
            for (int mf = 0; mf < 4; mf++)
#pragma unroll
                for (int nf = 0; nf < 4; nf++) {
                    int p = nf >> 1, o = nf & 1;
                    mma_tf32(acc[mf][nf], a[mf], b[p][o], b[p][2 + o]);
                }
        }
    }

    // Epilogue: direct float2 stores + bias.
    const int crow = lid >> 2;          // 0..7
    const int ccol = 2 * (lid & 3);     // 0,2,4,6
#pragma unroll
    for (int nf = 0; nf < 4; nf++) {
        int col = n0 + wn + nf * 8 + ccol;
        float2 bv = *(const float2*)(bias + col);
#pragma unroll
        for (int mf = 0; mf < 4; mf++) {
            int row = m0 + wm + mf * 16 + crow;
            float2 v0 = make_float2(acc[mf][nf][0] + bv.x, acc[mf][nf][1] + bv.y);
            float2 v1 = make_float2(acc[mf][nf][2] + bv.x, acc[mf][nf][3] + bv.y);
            *(float2*)(C + (size_t)row * NDIM + col) = v0;
            *(float2*)(C + (size_t)(row + 8) * NDIM + col) = v1;
        }
    }
}

// ---------------- Launch ----------------------------------------------------

extern "C" void kernel_launch(void* const* d_in, const int* in_sizes, int n_in,
                              void* d_out, int out_size) {
    const float* x    = (const float*)d_in[0];   // (4, 2048, 4096) fp32
    const float* circ = (const float*)d_in[1];   // (512, 512, 8)   fp32
    const float* bias = (const float*)d_in[2];   // (4096,)         fp32
    float* out = (float*)d_out;                  // (4, 2048, 4096) fp32

    round_x_kernel<<<(MDIM * KDIM / 4) / 256, 256>>>((const float4*)x);
    expand_w_kernel<<<(NDIM * 512) / 256, 256>>>(circ);

    cudaFuncSetAttribute(bc_gemm, cudaFuncAttributeMaxDynamicSharedMemorySize,
                         SMEM_TOTAL);
    dim3 grid((MDIM / BM) * (NDIM / BN));        // 2048 CTAs
    bc_gemm<<<grid, THREADS, SMEM_TOTAL>>>(bias, out);
    (void)in_sizes; (void)n_in; (void)out_size;
}

// round 5
// speedup vs baseline: 5.7077x; 5.7077x over previous
#include <cuda_runtime.h>
#include <cstdint>
#include <cstddef>

// ----------------------------------------------------------------------------
// BlockCirculantLinear on GB300 (sm_103a; PTX target lacks 'a' => no tcgen05;
// legacy mma.sync m16n8k8 tf32 path, which R3 showed is issue-rate-limited).
// R4: compute in the 8-point rfft domain (convolution theorem) => 4.57x fewer
// tensor-core instructions than the densified GEMM.
//   Jobs (real GEMMs, M=8192, N=512):
//     job0: X0 *C0            (K=512)   job1: X4 *C4            (K=512)
//     job2/3: freq1 Re/Im     (K=1024)  job4/5: freq2 Re/Im     (K=1024)
//     job6/7: freq3 Re/Im     (K=1024)
//   A row for pair p = [Xp_re(512) | Xp_im(512)] (pair0 = [X0|X4]).
// ----------------------------------------------------------------------------

#define BM 128
#define BN 128
#define BK 32
#define NSTAGE 3
#define MDIM 8192
#define NB 512              // blocks per feature dim
#define THREADS 256

static constexpr int AK      = 4096;                 // g_X row stride (4 pairs x 1024)
static constexpr int BK_ROW  = 1024;                 // g_B row stride
static constexpr size_t PLANE = (size_t)MDIM * NB;   // out-plane elements

static constexpr int TILE_BYTES  = BM * BK * 4;          // 16384
static constexpr int STAGE_BYTES = 2 * TILE_BYTES;       // 32768
static constexpr int SMEM_TOTAL  = NSTAGE * STAGE_BYTES; // 98304

__device__ float g_X[(size_t)MDIM * AK];            // 134MB freq-domain x (tf32)
__device__ float g_B[(size_t)8 * NB * BK_ROW];      // 16.8MB freq-domain weights
__device__ float g_O[(size_t)8 * PLANE];            // 134MB GEMM outputs

// ---------------- helpers ---------------------------------------------------

__device__ __forceinline__ uint32_t smem_u32(const void* p) {
    uint32_t a;
    asm("{ .reg .u64 t; cvta.to.shared.u64 t, %1; cvt.u32.u64 %0, t; }"
        : "=r"(a) : "l"(p));
    return a;
}

#define SWZ(off) ((off) ^ (((off) >> 3) & 0x70))

__device__ __forceinline__ void cp_async16(uint32_t dst, const float* src) {
    asm volatile("cp.async.cg.shared.global [%0], [%1], 16;" :: "r"(dst), "l"(src));
}
__device__ __forceinline__ void cp_commit() {
    asm volatile("cp.async.commit_group;" ::: "memory");
}
template <int N> __device__ __forceinline__ void cp_wait() {
    asm volatile("cp.async.wait_group %0;" :: "n"(N) : "memory");
}

__device__ __forceinline__ float tf32r(float x) {
    uint32_t u;
    asm("cvt.rna.tf32.f32 %0, %1;" : "=r"(u) : "f"(x));
    return __uint_as_float(u);
}

__device__ __forceinline__ void ldsm4(uint32_t* r, uint32_t addr) {
    asm volatile("ldmatrix.sync.aligned.m8n8.x4.shared.b16 {%0,%1,%2,%3}, [%4];"
                 : "=r"(r[0]), "=r"(r[1]), "=r"(r[2]), "=r"(r[3]) : "r"(addr));
}

__device__ __forceinline__ void mma_tf32(float* c, const uint32_t* a,
                                         uint32_t b0, uint32_t b1) {
    asm volatile(
        "mma.sync.aligned.m16n8k8.row.col.f32.tf32.tf32.f32 "
        "{%0,%1,%2,%3}, {%4,%5,%6,%7}, {%8,%9}, {%0,%1,%2,%3};"
        : "+f"(c[0]), "+f"(c[1]), "+f"(c[2]), "+f"(c[3])
        : "r"(a[0]), "r"(a[1]), "r"(a[2]), "r"(a[3]), "r"(b0), "r"(b1));
}

#define FFT8(x0,x1,x2,x3,x4,x5,x6,x7, R0,R4,R1,I1,R2,I2,R3,I3)                \
    {                                                                         \
        const float cc = 0.70710678118654752440f;                             \
        float s04 = (x0) + (x4), d04 = (x0) - (x4);                           \
        float s26 = (x2) + (x6), d26 = (x2) - (x6);                           \
        float s15 = (x1) + (x5), d15 = (x1) - (x5);                           \
        float s37 = (x3) + (x7), d37 = (x3) - (x7);                           \
        R0 = s04 + s26 + s15 + s37;                                           \
        R4 = s04 + s26 - s15 - s37;                                           \
        R2 = s04 - s26;                                                       \
        I2 = s37 - s15;                                                       \
        float e = cc * (d15 - d37), o = cc * (d15 + d37);                     \
        R1 = d04 + e;  I1 = -d26 - o;                                         \
        R3 = d04 - e;  I3 =  d26 - o;                                         \
    }

// ---------------- Kernel 1: x -> freq planes (tf32-rounded) -----------------
// thread = (m, ib). g_X[m][pair][2][512]: [X0|X4 | X1re|X1im | X2re|X2im | X3re|X3im]
__global__ void fftx_kernel(const float4* __restrict__ x4) {
    int t  = blockIdx.x * blockDim.x + threadIdx.x;  // MDIM*NB
    int m  = t >> 9;
    int ib = t & 511;
    float4 a = x4[(size_t)m * 1024 + ib * 2];
    float4 b = x4[(size_t)m * 1024 + ib * 2 + 1];
    float R0, R4, R1, I1, R2, I2, R3, I3;
    FFT8(a.x, a.y, a.z, a.w, b.x, b.y, b.z, b.w, R0, R4, R1, I1, R2, I2, R3, I3);
    float* p = g_X + (size_t)m * AK + ib;
    p[0]        = tf32r(R0);
    p[512]      = tf32r(R4);
    p[1024]     = tf32r(R1);
    p[1536]     = tf32r(I1);
    p[2048]     = tf32r(R2);
    p[2560]     = tf32r(I2);
    p[3072]     = tf32r(R3);
    p[3584]     = tf32r(I3);
}

// ---------------- Kernel 2: circ -> freq weight job matrices ----------------
// thread = (nb, ib). B job layout: g_B[job][n=nb][k], k stride 1.
__global__ void fftc_kernel(const float* __restrict__ circ) {
    int t  = blockIdx.x * blockDim.x + threadIdx.x;  // NB*NB
    int nb = t >> 9;
    int ib = t & 511;
    const float* cp = circ + ((size_t)nb * NB + ib) * 8;
    float R0, R4, R1, I1, R2, I2, R3, I3;
    FFT8(cp[0], cp[1], cp[2], cp[3], cp[4], cp[5], cp[6], cp[7],
         R0, R4, R1, I1, R2, I2, R3, I3);
    R0 = tf32r(R0); R4 = tf32r(R4);
    R1 = tf32r(R1); I1 = tf32r(I1);
    R2 = tf32r(R2); I2 = tf32r(I2);
    R3 = tf32r(R3); I3 = tf32r(I3);
    const size_t JS = (size_t)NB * BK_ROW;           // job stride
    float* r = g_B + (size_t)nb * BK_ROW + ib;
    r[0 * JS]       = R0;                            // job0: C0 (k<512)
    r[1 * JS]       = R4;                            // job1: C4 (k<512)
    r[2 * JS]       = R1;  r[2 * JS + 512] = -I1;    // job2: [C1re; -C1im]
    r[3 * JS]       = I1;  r[3 * JS + 512] =  R1;    // job3: [C1im;  C1re]
    r[4 * JS]       = R2;  r[4 * JS + 512] = -I2;
    r[5 * JS]       = I2;  r[5 * JS + 512] =  R2;
    r[6 * JS]       = R3;  r[6 * JS + 512] = -I3;
    r[7 * JS]       = I3;  r[7 * JS + 512] =  R3;
}

// ---------------- Kernel 3: batched TF32 mma.sync GEMM ----------------------
// 8 jobs x 64 m-tiles x 4 n-tiles. 8 warps as 2(m) x 4(n), warp tile 64x32.
__global__ void __launch_bounds__(THREADS) bc_gemm() {
    extern __shared__ char smem[];
    uint32_t sb0 = smem_u32(smem);
    const int tid = threadIdx.x;
    const int wid = tid >> 5;
    const int lid = tid & 31;
    const int wm = (wid >> 2) * 64;
    const int wn = (wid & 3) * 32;

    const int job = blockIdx.x >> 8;
    const int rem = blockIdx.x & 255;
    const int m0 = (rem & 63) * BM;
    const int n0 = (rem >> 6) * BN;
    const int NKIT = (job < 2) ? 16 : 32;            // K = 512 or 1024

    const float* Arow = g_X + (size_t)m0 * AK + (job >> 1) * 1024
                            + ((job == 1) ? 512 : 0);
    const float* Brow = g_B + (size_t)job * NB * BK_ROW + (size_t)n0 * BK_ROW;

    auto load_stage = [&](int s, int kiter) {
        uint32_t stg = sb0 + s * STAGE_BYTES;
        int k0 = kiter * BK;
#pragma unroll
        for (int q = 0; q < 4; q++) {
            int idx = tid + q * THREADS;
            int row = idx >> 3;
            int ch  = idx & 7;
            uint32_t sw = SWZ((uint32_t)(row * 128 + ch * 16));
            cp_async16(stg + sw,              Arow + (size_t)row * AK     + k0 + ch * 4);
            cp_async16(stg + TILE_BYTES + sw, Brow + (size_t)row * BK_ROW + k0 + ch * 4);
        }
        cp_commit();
    };

    float acc[4][4][4];
#pragma unroll
    for (int mf = 0; mf < 4; mf++)
#pragma unroll
        for (int nf = 0; nf < 4; nf++)
#pragma unroll
            for (int r = 0; r < 4; r++) acc[mf][nf][r] = 0.0f;

    load_stage(0, 0);
    load_stage(1, 1);

    const int lrow = lid & 15;
    const int lcol = (lid >> 4) * 16;

    for (int i = 0; i < NKIT; i++) {
        cp_wait<1>();
        __syncthreads();
        if (i + 2 < NKIT) load_stage((i + 2) % NSTAGE, i + 2);

        uint32_t Ab = sb0 + (i % NSTAGE) * STAGE_BYTES;
        uint32_t Bb = Ab + TILE_BYTES;

#pragma unroll
        for (int ks = 0; ks < 4; ks++) {
            uint32_t a[4][4];
#pragma unroll
            for (int mf = 0; mf < 4; mf++) {
                uint32_t off = (uint32_t)((wm + mf * 16 + lrow) * 128 + ks * 32 + lcol);
                ldsm4(a[mf], Ab + SWZ(off));
            }
            uint32_t b[2][4];
#pragma unroll
            for (int p = 0; p < 2; p++) {
                uint32_t off = (uint32_t)((wn + p * 16 + lrow) * 128 + ks * 32 + lcol);
                ldsm4(b[p], Bb + SWZ(off));
            }
#pragma unroll
            for (int mf = 0; mf < 4; mf++)
#pragma unroll
                for (int nf = 0; nf < 4; nf++) {
                    int p = nf >> 1, o = nf & 1;
                    mma_tf32(acc[mf][nf], a[mf], b[p][o], b[p][2 + o]);
                }
        }
    }

    // Epilogue: store to this job's output plane (row stride NB=512).
    float* O = g_O + (size_t)job * PLANE;
    const int crow = lid >> 2;
    const int ccol = 2 * (lid & 3);
#pragma unroll
    for (int nf = 0; nf < 4; nf++) {
        int col = n0 + wn + nf * 8 + ccol;
#pragma unroll
        for (int mf = 0; mf < 4; mf++) {
            int row = m0 + wm + mf * 16 + crow;
            *(float2*)(O + (size_t)row * NB + col) =
                make_float2(acc[mf][nf][0], acc[mf][nf][1]);
            *(float2*)(O + (size_t)(row + 8) * NB + col) =
                make_float2(acc[mf][nf][2], acc[mf][nf][3]);
        }
    }
}

// ---------------- Kernel 4: inverse 8-pt rfft + bias ------------------------
// thread = (m, nb). Planes: 0:Y0 1:Y4 2:R1 3:I1 4:R2 5:I2 6:R3 7:I3.
__global__ void ifft_kernel(const float* __restrict__ bias,
                            float* __restrict__ out) {
    int t  = blockIdx.x * blockDim.x + threadIdx.x;  // MDIM*NB
    int m  = t >> 9;
    int nb = t & 511;
    const float* p = g_O + (size_t)m * NB + nb;
    float R0 = p[0 * PLANE], R4 = p[1 * PLANE];
    float R1 = p[2 * PLANE], I1 = p[3 * PLANE];
    float R2 = p[4 * PLANE], I2 = p[5 * PLANE];
    float R3 = p[6 * PLANE], I3 = p[7 * PLANE];

    const float cc = 0.70710678118654752440f;
    float se = R0 + R4, so = R0 - R4;
    float y0 = se + 2.0f * ( R1 + R2 + R3);
    float y2 = se + 2.0f * (-I1 - R2 + I3);
    float y4 = se + 2.0f * (-R1 + R2 - R3);
    float y6 = se + 2.0f * ( I1 - R2 - I3);
    float a1 = cc * (R1 - I1), b1 = cc * (R1 + I1);
    float a3 = cc * (R3 - I3), b3 = cc * (R3 + I3);
    float y1 = so + 2.0f * ( a1 - I2 - b3);
    float y3 = so + 2.0f * (-b1 + I2 + a3);
    float y5 = so + 2.0f * (-a1 - I2 + b3);
    float y7 = so + 2.0f * ( b1 + I2 - a3);

    const float4 bv0 = *(const float4*)(bias + nb * 8);
    const float4 bv1 = *(const float4*)(bias + nb * 8 + 4);
    float4* dst = (float4*)(out + (size_t)m * 4096 + nb * 8);
    dst[0] = make_float4(0.125f * y0 + bv0.x, 0.125f * y1 + bv0.y,
                         0.125f * y2 + bv0.z, 0.125f * y3 + bv0.w);
    dst[1] = make_float4(0.125f * y4 + bv1.x, 0.125f * y5 + bv1.y,
                         0.125f * y6 + bv1.z, 0.125f * y7 + bv1.w);
}

// ---------------- Launch ----------------------------------------------------

extern "C" void kernel_launch(void* const* d_in, const int* in_sizes, int n_in,
                              void* d_out, int out_size) {
    const float* x    = (const float*)d_in[0];
    const float* circ = (const float*)d_in[1];
    const float* bias = (const float*)d_in[2];
    float* out = (float*)d_out;

    fftx_kernel<<<(MDIM * NB) / 256, 256>>>((const float4*)x);
    fftc_kernel<<<(NB * NB) / 256, 256>>>(circ);

    cudaFuncSetAttribute(bc_gemm, cudaFuncAttributeMaxDynamicSharedMemorySize,
                         SMEM_TOTAL);
    bc_gemm<<<8 * 64 * 4, THREADS, SMEM_TOTAL>>>();   // 2048 CTAs

    ifft_kernel<<<(MDIM * NB) / 256, 256>>>(bias, out);
    (void)in_sizes; (void)n_in; (void)out_size;
}